// round 8
// baseline (speedup 1.0000x reference)
#include <cuda_runtime.h>
#include <cuda_bf16.h>
#include <cstdint>

#define Bb 4
#define Nn 512
#define Hh 8

// ---------------- device scratch ----------------
__device__ float          g_preg[Bb * 128];
__device__ __nv_bfloat16  g_wetbf[128 * 128];                // we_w^T [m][k] bf16
__device__ __nv_bfloat16  g_pre1bf[Bb * Nn * 128];           // pre1 (j-dependent) bf16
__device__ float          g_prerow[Bb * Nn * 128];           // pre2+pre_g+we_b (i-dependent)
__device__ float          g_val[Bb * Nn * 128];
__device__ float          g_skip[Bb * Nn * 128];
__device__ float          g_logits[(size_t)Bb * Hh * Nn * Nn]; // final coefs

// ---------------- helpers ----------------
__device__ __forceinline__ void mma_bf16(float acc[4],
                                         unsigned a0, unsigned a1, unsigned a2, unsigned a3,
                                         unsigned b0, unsigned b1) {
    asm volatile(
        "mma.sync.aligned.m16n8k16.row.col.f32.bf16.bf16.f32 "
        "{%0,%1,%2,%3},{%4,%5,%6,%7},{%8,%9},{%0,%1,%2,%3};\n"
        : "+f"(acc[0]), "+f"(acc[1]), "+f"(acc[2]), "+f"(acc[3])
        : "r"(a0), "r"(a1), "r"(a2), "r"(a3), "r"(b0), "r"(b1));
}
__device__ __forceinline__ void ldsm_x4(unsigned& r0, unsigned& r1, unsigned& r2, unsigned& r3,
                                        uint32_t addr) {
    asm volatile("ldmatrix.sync.aligned.m8n8.x4.shared.b16 {%0,%1,%2,%3}, [%4];\n"
                 : "=r"(r0), "=r"(r1), "=r"(r2), "=r"(r3) : "r"(addr));
}
__device__ __forceinline__ uint32_t smem_u32(const void* p) {
    uint32_t a;
    asm("{ .reg .u64 t; cvta.to.shared.u64 t, %1; cvt.u32.u64 %0, t; }" : "=r"(a) : "l"(p));
    return a;
}
__device__ __forceinline__ void cp16(uint32_t dst, const void* src) {
    asm volatile("cp.async.cg.shared.global [%0], [%1], 16;" :: "r"(dst), "l"(src));
}
#define CP_COMMIT() asm volatile("cp.async.commit_group;" ::: "memory")
#define CP_WAIT0()  asm volatile("cp.async.wait_group 0;" ::: "memory")

// smem layout (bytes)
#define OFF_SW    0          // we^T bf16 [128][136]            34816
#define OFF_SE    34816      // edge bf16 [128][136]            34816
#define OFF_SF    69632      // edge fp32 staging [128][128]    65536
#define OFF_SP    135168     // pre1 bf16 2 x [128][136]        69632
#define OFF_LOG   204800     // logits [8][512] f32             16384
#define OFF_PRE   221184     // 128 f32
#define OFF_AW    221696     // 128 f32
#define OFF_AB    222208     // 8 f32
#define OFF_ADJ   222240     // 512 f32
#define EDGE_SMEM 224288

// ---------------- kernel 1: pre_g + we_w^T bf16 ----------------
__global__ void prep_k(const float* __restrict__ graph, const float* __restrict__ wg_w,
                       const float* __restrict__ wg_b, const float* __restrict__ we_w) {
    int blk = blockIdx.x;
    int t = threadIdx.x;
    if (blk < 4) {
        float s = wg_b[t];
        #pragma unroll 4
        for (int k = 0; k < 128; k++)
            s = fmaf(graph[blk * 128 + k], wg_w[k * 128 + t], s);
        g_preg[blk * 128 + t] = s;
    } else {
        int base = (blk - 4) * 4096;
        #pragma unroll
        for (int it = 0; it < 32; it++) {
            int idx = base + t + it * 128;
            int k = idx >> 7, m = idx & 127;
            g_wetbf[m * 128 + k] = __float2bfloat16(we_w[idx]);
        }
    }
}

// ---------------- kernel 2: node precompute ----------------
__global__ void node_k(const float* __restrict__ node,
                       const float* __restrict__ m_w, const float* __restrict__ m_b,
                       const float* __restrict__ skip_w, const float* __restrict__ skip_b,
                       const float* __restrict__ w1_w, const float* __restrict__ w1_b,
                       const float* __restrict__ w2_w, const float* __restrict__ w2_b,
                       const float* __restrict__ we_b) {
    __shared__ float sn[8][128];
    int blk = blockIdx.x;
    int b = blk >> 6;
    int n0 = (blk & 63) * 8;
    int t = threadIdx.x;

    float4* snv = (float4*)sn;
    const float4* gn = (const float4*)(node + ((size_t)(b * 512) + n0) * 128);
    snv[t] = gn[t];
    snv[t + 128] = gn[t + 128];
    __syncthreads();

    int o = t;
    float av[8], as_[8], a1[8], a2[8];
    #pragma unroll
    for (int nn = 0; nn < 8; nn++) { av[nn] = 0.f; as_[nn] = 0.f; a1[nn] = 0.f; a2[nn] = 0.f; }

    for (int k = 0; k < 128; k++) {
        float wm = m_w[k * 128 + o];
        float ws = skip_w[k * 128 + o];
        float w1 = w1_w[k * 128 + o];
        float w2 = w2_w[k * 128 + o];
        #pragma unroll
        for (int nn = 0; nn < 8; nn++) {
            float x = sn[nn][k];
            av[nn]  = fmaf(x, wm, av[nn]);
            as_[nn] = fmaf(x, ws, as_[nn]);
            a1[nn]  = fmaf(x, w1, a1[nn]);
            a2[nn]  = fmaf(x, w2, a2[nn]);
        }
    }
    float addc = g_preg[b * 128 + o] + we_b[o];
    #pragma unroll
    for (int nn = 0; nn < 8; nn++) {
        size_t base = ((size_t)(b * 512) + n0 + nn) * 128 + o;
        g_val[base]    = av[nn] + m_b[o];
        g_skip[base]   = as_[nn] + skip_b[o];
        g_pre1bf[base] = __float2bfloat16(a1[nn] + w1_b[o]);
        g_prerow[base] = a2[nn] + w2_b[o] + addc;
    }
}

// ---------------- kernel 3: edge GEMM + logits + fused softmax ----------------
// block = (b,i), 512 threads = 16 warps: 8 j-blocks(16) x 2 m-blocks(64).
__global__ void __launch_bounds__(512, 1) edge_k(const float* __restrict__ edge,
                                                 const float* __restrict__ adj,
                                                 const float* __restrict__ a_w,
                                                 const float* __restrict__ a_b) {
    extern __shared__ char sm[];
    uint32_t smb = smem_u32(sm);
    float* sPre = (float*)(sm + OFF_PRE);
    float* sAw  = (float*)(sm + OFF_AW);
    float* sAb  = (float*)(sm + OFF_AB);
    float* sAdj = (float*)(sm + OFF_ADJ);
    float* sLog = (float*)(sm + OFF_LOG);

    int blk = blockIdx.x;
    int b = blk >> 9;
    int i = blk & 511;
    int t = threadIdx.x;
    int w = t >> 5;
    int lane = t & 31;

    if (t < 128) {
        sPre[t] = g_prerow[((size_t)(b * 512) + i) * 128 + t];
        sAw[t] = a_w[t];
        if (t < 8) sAb[t] = a_b[t];
        ((float4*)sAdj)[t] = ((const float4*)(adj + ((size_t)(b * 512) + i) * 512))[t];
    }

    const char* eBase = (const char*)(edge + (((size_t)(b * 512 + i)) * 512) * 128);
    const char* pBase = (const char*)(g_pre1bf + ((size_t)(b * 512)) * 128);

    { // group 0: sW + sF(tile0, full 64KB) + sP(tile0 -> buf0)
        const char* gw = (const char*)g_wetbf;
        #pragma unroll
        for (int it = 0; it < 4; it++) {
            int g = t + it * 512;
            int r = g >> 4, c = g & 15;
            cp16(smb + OFF_SW + r * 272 + c * 16, gw + g * 16);
        }
        #pragma unroll
        for (int it = 0; it < 8; it++) {
            int g = t + it * 512;
            cp16(smb + OFF_SF + g * 16, eBase + g * 16);
        }
        #pragma unroll
        for (int it = 0; it < 4; it++) {
            int g = t + it * 512;
            int r = g >> 4, c = g & 15;
            cp16(smb + OFF_SP + r * 272 + c * 16, pBase + g * 16);
        }
        CP_COMMIT();
    }

    int jb = (w & 7) << 4;
    int mb = (w >> 3) << 6;
    int qr = lane >> 2;
    int qc = (lane & 3) << 1;
    int h0 = mb >> 4;

    int row_a = jb + (lane & 7) + (((lane >> 3) & 1) << 3);
    int colc_a = ((lane >> 4) & 1) << 3;
    uint32_t aBase = smb + OFF_SE + (row_a * 136 + colc_a) * 2;
    uint32_t bBase[4];
    #pragma unroll
    for (int p = 0; p < 4; p++) {
        int row_b = mb + (((p << 1) + (lane >> 4)) << 3) + (lane & 7);
        bBase[p] = smb + OFF_SW + (row_b * 136 + (((lane >> 3) & 1) << 3)) * 2;
    }

    for (int tt = 0; tt < 4; tt++) {
        CP_WAIT0();
        __syncthreads();
        // convert sF(fp32) -> sE(bf16)
        const float4* sf = (const float4*)(sm + OFF_SF);
        #pragma unroll
        for (int it = 0; it < 8; it++) {
            int g = t + it * 512;
            int r = g >> 5, c4 = g & 31;
            float4 v = sf[g];
            __nv_bfloat162 p0 = __floats2bfloat162_rn(v.x, v.y);
            __nv_bfloat162 p1 = __floats2bfloat162_rn(v.z, v.w);
            uint2 u;
            u.x = *(uint32_t*)&p0;
            u.y = *(uint32_t*)&p1;
            *(uint2*)(sm + OFF_SE + r * 272 + c4 * 8) = u;
        }
        __syncthreads();
        // prefetch next tile (full 64KB edge + 32KB pre1)
        if (tt < 3) {
            const char* ge = eBase + (size_t)(tt + 1) * 65536;  // 128*128*4 B
            const char* gp = pBase + (size_t)(tt + 1) * 32768;  // 128*128*2 B
            uint32_t spDst = smb + OFF_SP + ((tt + 1) & 1) * 34816;
            #pragma unroll
            for (int it = 0; it < 8; it++) {
                int g = t + it * 512;
                cp16(smb + OFF_SF + g * 16, ge + g * 16);
            }
            #pragma unroll
            for (int it = 0; it < 4; it++) {
                int g = t + it * 512;
                int r = g >> 4, c = g & 15;
                cp16(spDst + r * 272 + c * 16, gp + g * 16);
            }
            CP_COMMIT();
        }

        float acc[8][4];
        #pragma unroll
        for (int nt = 0; nt < 8; nt++)
            #pragma unroll
            for (int q = 0; q < 4; q++) acc[nt][q] = 0.f;

        #pragma unroll
        for (int ks = 0; ks < 8; ks++) {
            unsigned a0, a1, a2, a3;
            ldsm_x4(a0, a1, a2, a3, aBase + ks * 32);
            #pragma unroll
            for (int p = 0; p < 4; p++) {
                unsigned b0, b1, b2, b3;
                ldsm_x4(b0, b1, b2, b3, bBase[p] + ks * 32);
                mma_bf16(acc[2 * p],     a0, a1, a2, a3, b0, b1);
                mma_bf16(acc[2 * p + 1], a0, a1, a2, a3, b2, b3);
            }
        }

        const __nv_bfloat16* sPb = (const __nv_bfloat16*)(sm + OFF_SP + (tt & 1) * 34816);
        #pragma unroll
        for (int hh = 0; hh < 4; hh++) {
            int h = h0 + hh;
            #pragma unroll
            for (int q2 = 0; q2 < 2; q2++) {
                int row = jb + qr + (q2 << 3);
                float s = 0.f;
                #pragma unroll
                for (int np = 0; np < 2; np++) {
                    int nt = hh * 2 + np;
                    #pragma unroll
                    for (int c0 = 0; c0 < 2; c0++) {
                        int m = mb + nt * 8 + qc + c0;
                        float p = acc[nt][q2 * 2 + c0] + sPre[m]
                                + __bfloat162float(sPb[row * 136 + m]);
                        p = (p > 0.f) ? p : 0.01f * p;
                        s = fmaf(p, sAw[m], s);
                    }
                }
                s += __shfl_xor_sync(0xffffffffu, s, 1);
                s += __shfl_xor_sync(0xffffffffu, s, 2);
                if ((lane & 3) == 0) {
                    int j = tt * 128 + row;
                    sLog[h * 512 + j] = s + sAb[h] + (sAdj[j] - 1.0f) * 1e9f;
                }
            }
        }
    }

    __syncthreads();
    // fused masked softmax: warp w < 8 handles head w
    if (w < 8) {
        int h = w;
        float x[16];
        #pragma unroll
        for (int k = 0; k < 16; k++) x[k] = sLog[h * 512 + lane + k * 32];
        float m = x[0];
        #pragma unroll
        for (int k = 1; k < 16; k++) m = fmaxf(m, x[k]);
        #pragma unroll
        for (int off = 16; off > 0; off >>= 1)
            m = fmaxf(m, __shfl_xor_sync(0xffffffffu, m, off));
        float e[16], s = 0.f;
        #pragma unroll
        for (int k = 0; k < 16; k++) { e[k] = __expf(x[k] - m); s += e[k]; }
        #pragma unroll
        for (int off = 16; off > 0; off >>= 1)
            s += __shfl_xor_sync(0xffffffffu, s, off);
        float inv = 1.0f / s;
        float* dst = g_logits + ((size_t)((b * 8 + h) * 512 + i)) * 512;
        #pragma unroll
        for (int k = 0; k < 16; k++) dst[lane + k * 32] = e[k] * inv;
    }
}

// ---------------- kernel 4: coefs @ values + skip + relu + layernorm ----------------
// block = (b, 2 i's), 512 threads. thread = (j-quarter, o). Verified layout:
// sc[ii][h][j]: float4 index q = ii*1024 + h*128 + c  ->  ii=q>>10, h=(q>>7)&7, c=q&127.
__global__ void __launch_bounds__(512) out_k(const float* __restrict__ ln_scale,
                                             const float* __restrict__ ln_offset,
                                             float* __restrict__ out) {
    __shared__ float sc[2][8][512];      // 32 KB
    __shared__ float sacc[4][2][128];    // 4 KB
    __shared__ float red[2][4][2];
    int blk = blockIdx.x;
    int b = blk >> 8;                    // 0..3
    int i0 = (blk & 255) * 2;            // 0..510
    int t = threadIdx.x;

    { // stage coefs for 2 i's x 8 heads x 512 j  (2048 float4)
        float4* scv = (float4*)sc;
        const float4* gl = (const float4*)g_logits;
        #pragma unroll
        for (int it = 0; it < 4; it++) {
            int q = t + it * 512;               // 0..2047
            int ii = q >> 10;                   // 0..1
            int h = (q >> 7) & 7;               // 0..7
            int c = q & 127;                    // float4 within 512-j row
            scv[q] = gl[((size_t)((b * 8 + h) * 512) + i0 + ii) * 128 + c];
        }
    }
    __syncthreads();

    {
        int o = t & 127;
        int jq = t >> 7;                        // 0..3 j-quarter
        int h = o >> 4;
        const float* vb = g_val + (size_t)b * 65536 + (size_t)(jq * 128) * 128 + o;
        const float* cf0 = &sc[0][h][jq * 128];
        const float* cf1 = &sc[1][h][jq * 128];
        float a0 = 0.f, a1 = 0.f;
        #pragma unroll 8
        for (int j = 0; j < 128; j++) {
            float v = vb[(size_t)j * 128];
            a0 = fmaf(cf0[j], v, a0);
            a1 = fmaf(cf1[j], v, a1);
        }
        sacc[jq][0][o] = a0;
        sacc[jq][1][o] = a1;
    }
    __syncthreads();

    int lane = t & 31;
    int o2 = t & 127;
    int i2 = (t >> 7) & 1;
    bool active = t < 256;
    float r = 0.f;
    size_t base = ((size_t)(b * 512) + i0 + i2) * 128 + o2;
    if (active) {
        r = sacc[0][i2][o2] + sacc[1][i2][o2] + sacc[2][i2][o2] + sacc[3][i2][o2]
          + g_skip[base];
        r = fmaxf(r, 0.f);
        float s1 = r, s2 = r * r;
        #pragma unroll
        for (int off = 16; off > 0; off >>= 1) {
            s1 += __shfl_xor_sync(0xffffffffu, s1, off);
            s2 += __shfl_xor_sync(0xffffffffu, s2, off);
        }
        if (lane == 0) {
            int wq = (t >> 5) & 3;               // warp's o-chunk within the 128
            red[i2][wq][0] = s1;
            red[i2][wq][1] = s2;
        }
    }
    __syncthreads();
    if (active) {
        float s1 = red[i2][0][0] + red[i2][1][0] + red[i2][2][0] + red[i2][3][0];
        float s2 = red[i2][0][1] + red[i2][1][1] + red[i2][2][1] + red[i2][3][1];
        float mean = s1 * (1.0f / 128.0f);
        float var = s2 * (1.0f / 128.0f) - mean * mean;
        out[base] = (r - mean) * rsqrtf(var + 1e-5f) * ln_scale[o2] + ln_offset[o2];
    }
}

// ---------------- launch ----------------
extern "C" void kernel_launch(void* const* d_in, const int* in_sizes, int n_in,
                              void* d_out, int out_size) {
    const float* node   = (const float*)d_in[0];
    const float* edge   = (const float*)d_in[1];
    const float* graph  = (const float*)d_in[2];
    const float* adj    = (const float*)d_in[3];
    const float* m_w    = (const float*)d_in[5];
    const float* m_b    = (const float*)d_in[6];
    const float* skip_w = (const float*)d_in[7];
    const float* skip_b = (const float*)d_in[8];
    const float* w1_w   = (const float*)d_in[9];
    const float* w1_b   = (const float*)d_in[10];
    const float* w2_w   = (const float*)d_in[11];
    const float* w2_b   = (const float*)d_in[12];
    const float* we_w   = (const float*)d_in[13];
    const float* we_b   = (const float*)d_in[14];
    const float* wg_w   = (const float*)d_in[15];
    const float* wg_b   = (const float*)d_in[16];
    const float* a_w    = (const float*)d_in[17];
    const float* a_b    = (const float*)d_in[18];
    const float* ln_s   = (const float*)d_in[19];
    const float* ln_o   = (const float*)d_in[20];
    float* out = (float*)d_out;

    cudaFuncSetAttribute(edge_k, cudaFuncAttributeMaxDynamicSharedMemorySize, EDGE_SMEM);

    prep_k<<<8, 128>>>(graph, wg_w, wg_b, we_w);
    node_k<<<256, 128>>>(node, m_w, m_b, skip_w, skip_b, w1_w, w1_b, w2_w, w2_b, we_b);
    edge_k<<<2048, 512, EDGE_SMEM>>>(edge, adj, a_w, a_b);
    out_k<<<1024, 512>>>(ln_s, ln_o, out);
}

// round 9
// speedup vs baseline: 1.3952x; 1.3952x over previous
#include <cuda_runtime.h>
#include <cuda_bf16.h>
#include <cstdint>

#define Bb 4
#define Nn 512
#define Hh 8

// ---------------- device scratch ----------------
__device__ float          g_preg[Bb * 128];
__device__ __nv_bfloat16  g_wetbf[128 * 128];                // we_w^T [m][k] bf16
__device__ __nv_bfloat16  g_pre1bf[Bb * Nn * 128];           // pre1 (j-dependent) bf16
__device__ float          g_prerow[Bb * Nn * 128];           // pre2+pre_g+we_b (i-dependent)
__device__ float          g_val[Bb * Nn * 128];
__device__ float          g_skip[Bb * Nn * 128];
__device__ float          g_logits[(size_t)Bb * Hh * Nn * Nn]; // masked logits -> coefs

// ---------------- helpers ----------------
__device__ __forceinline__ void mma_bf16(float acc[4],
                                         unsigned a0, unsigned a1, unsigned a2, unsigned a3,
                                         unsigned b0, unsigned b1) {
    asm volatile(
        "mma.sync.aligned.m16n8k16.row.col.f32.bf16.bf16.f32 "
        "{%0,%1,%2,%3},{%4,%5,%6,%7},{%8,%9},{%0,%1,%2,%3};\n"
        : "+f"(acc[0]), "+f"(acc[1]), "+f"(acc[2]), "+f"(acc[3])
        : "r"(a0), "r"(a1), "r"(a2), "r"(a3), "r"(b0), "r"(b1));
}
__device__ __forceinline__ void ldsm_x4(unsigned& r0, unsigned& r1, unsigned& r2, unsigned& r3,
                                        unsigned addr) {
    asm volatile("ldmatrix.sync.aligned.m8n8.x4.shared.b16 {%0,%1,%2,%3}, [%4];\n"
                 : "=r"(r0), "=r"(r1), "=r"(r2), "=r"(r3) : "r"(addr));
}

// ---------------- kernel 1: pre_g + we_w^T bf16 ----------------
__global__ void prep_k(const float* __restrict__ graph, const float* __restrict__ wg_w,
                       const float* __restrict__ wg_b, const float* __restrict__ we_w) {
    int blk = blockIdx.x;
    int t = threadIdx.x;
    if (blk < 4) {
        float s = wg_b[t];
        #pragma unroll 4
        for (int k = 0; k < 128; k++)
            s = fmaf(graph[blk * 128 + k], wg_w[k * 128 + t], s);
        g_preg[blk * 128 + t] = s;
    } else {
        int base = (blk - 4) * 4096;
        #pragma unroll
        for (int it = 0; it < 32; it++) {
            int idx = base + t + it * 128;
            int k = idx >> 7, m = idx & 127;
            g_wetbf[m * 128 + k] = __float2bfloat16(we_w[idx]);
        }
    }
}

// ---------------- kernel 2: node precompute ----------------
__global__ void node_k(const float* __restrict__ node,
                       const float* __restrict__ m_w, const float* __restrict__ m_b,
                       const float* __restrict__ skip_w, const float* __restrict__ skip_b,
                       const float* __restrict__ w1_w, const float* __restrict__ w1_b,
                       const float* __restrict__ w2_w, const float* __restrict__ w2_b,
                       const float* __restrict__ we_b) {
    __shared__ float sn[8][128];
    int blk = blockIdx.x;
    int b = blk >> 6;
    int n0 = (blk & 63) * 8;
    int t = threadIdx.x;

    float4* snv = (float4*)sn;
    const float4* gn = (const float4*)(node + ((size_t)(b * 512) + n0) * 128);
    snv[t] = gn[t];
    snv[t + 128] = gn[t + 128];
    __syncthreads();

    int o = t;
    float av[8], as_[8], a1[8], a2[8];
    #pragma unroll
    for (int nn = 0; nn < 8; nn++) { av[nn] = 0.f; as_[nn] = 0.f; a1[nn] = 0.f; a2[nn] = 0.f; }

    for (int k = 0; k < 128; k++) {
        float wm = m_w[k * 128 + o];
        float ws = skip_w[k * 128 + o];
        float w1 = w1_w[k * 128 + o];
        float w2 = w2_w[k * 128 + o];
        #pragma unroll
        for (int nn = 0; nn < 8; nn++) {
            float x = sn[nn][k];
            av[nn]  = fmaf(x, wm, av[nn]);
            as_[nn] = fmaf(x, ws, as_[nn]);
            a1[nn]  = fmaf(x, w1, a1[nn]);
            a2[nn]  = fmaf(x, w2, a2[nn]);
        }
    }
    float addc = g_preg[b * 128 + o] + we_b[o];
    #pragma unroll
    for (int nn = 0; nn < 8; nn++) {
        size_t base = ((size_t)(b * 512) + n0 + nn) * 128 + o;
        g_val[base]    = av[nn] + m_b[o];
        g_skip[base]   = as_[nn] + skip_b[o];
        g_pre1bf[base] = __float2bfloat16(a1[nn] + w1_b[o]);
        g_prerow[base] = a2[nn] + w2_b[o] + addc;
    }
}

// ---------------- kernel 3: edge GEMM (bf16 mma) + masked-logit epilogue ----------------
// block = (b, i); 256 threads = 8 warps; warp w: j-block (w&3)*16, m-block (w>>2)*64.
// Single-buffered 64-j tiles, occupancy 3.
__global__ void __launch_bounds__(256, 3) edge_k(const float* __restrict__ edge,
                                                 const float* __restrict__ adj,
                                                 const float* __restrict__ a_w,
                                                 const float* __restrict__ a_b) {
    extern __shared__ char smraw[];
    __nv_bfloat16* sW = (__nv_bfloat16*)smraw;    // [128][136]  34816 B
    __nv_bfloat16* sE = sW + 128 * 136;           // [64][136]   17408 B
    __nv_bfloat16* sP = sE + 64 * 136;            // [64][136]   17408 B
    float* sPre = (float*)(sP + 64 * 136);        // [128]
    float* sAw  = sPre + 128;                     // [128]
    float* sAb  = sAw + 128;                      // [8]
    float* sAdj = sAb + 8;                        // [512]

    int blk = blockIdx.x;
    int b = blk >> 9;
    int i = blk & 511;
    int t = threadIdx.x;
    int w = t >> 5;
    int lane = t & 31;

    { // stage we_w^T : 2048 uint4
        const uint4* gw = (const uint4*)g_wetbf;
        #pragma unroll
        for (int it = 0; it < 8; it++) {
            int idx = t + it * 256;
            int r = idx >> 4, c = idx & 15;
            *(uint4*)(sW + r * 136 + c * 8) = gw[idx];
        }
    }
    if (t < 128) {
        sPre[t] = g_prerow[((size_t)(b * 512) + i) * 128 + t];
        sAw[t] = a_w[t];
        ((float4*)sAdj)[t] = ((const float4*)(adj + ((size_t)(b * 512) + i) * 512))[t];
    }
    if (t < 8) sAb[t] = a_b[t];

    int jb = (w & 3) << 4;
    int mb = (w >> 2) << 6;
    int qr = lane >> 2;
    int qc = (lane & 3) << 1;
    int h0 = mb >> 4;

    // ldmatrix lane addressing
    int row_a = jb + (lane & 7) + (((lane >> 3) & 1) << 3);
    int colc_a = ((lane >> 4) & 1) << 3;
    unsigned aBase = (unsigned)__cvta_generic_to_shared(sE + row_a * 136 + colc_a);
    unsigned bBase[4];
    #pragma unroll
    for (int p = 0; p < 4; p++) {
        int row_b = mb + (((p << 1) + (lane >> 4)) << 3) + (lane & 7);
        bBase[p] = (unsigned)__cvta_generic_to_shared(sW + row_b * 136 + (((lane >> 3) & 1) << 3));
    }

    for (int tt = 0; tt < 8; tt++) {
        int j0 = tt * 64;
        __syncthreads();
        // edge tile -> bf16 smem (fp32 load, convert)
        const float4* ge = (const float4*)(edge + (((size_t)(b * 512 + i)) * 512 + j0) * 128);
        #pragma unroll
        for (int it = 0; it < 8; it++) {
            int idx = t + it * 256;            // 0..2047 float4
            int r = idx >> 5, c = idx & 31;
            float4 v = ge[idx];
            __nv_bfloat162 p0 = __floats2bfloat162_rn(v.x, v.y);
            __nv_bfloat162 p1 = __floats2bfloat162_rn(v.z, v.w);
            uint2 u;
            u.x = *(unsigned*)&p0;
            u.y = *(unsigned*)&p1;
            *(uint2*)(sE + r * 136 + c * 4) = u;
        }
        { // pre1 tile (bf16): 1024 uint4
            const uint4* gp = (const uint4*)(g_pre1bf + ((size_t)(b * 512) + j0) * 128);
            #pragma unroll
            for (int it = 0; it < 4; it++) {
                int idx = t + it * 256;
                int r = idx >> 4, c = idx & 15;
                *(uint4*)(sP + r * 136 + c * 8) = gp[idx];
            }
        }
        __syncthreads();

        float acc[8][4];
        #pragma unroll
        for (int nt = 0; nt < 8; nt++)
            #pragma unroll
            for (int q = 0; q < 4; q++) acc[nt][q] = 0.f;

        #pragma unroll
        for (int ks = 0; ks < 8; ks++) {
            unsigned a0, a1, a2, a3;
            ldsm_x4(a0, a1, a2, a3, aBase + ks * 32);
            #pragma unroll
            for (int p = 0; p < 4; p++) {
                unsigned b0, b1, b2, b3;
                ldsm_x4(b0, b1, b2, b3, bBase[p] + ks * 32);
                mma_bf16(acc[2 * p],     a0, a1, a2, a3, b0, b1);
                mma_bf16(acc[2 * p + 1], a0, a1, a2, a3, b2, b3);
            }
        }

        // epilogue: + prerow(i) + pre1(j), leaky_relu, a_w contraction, +mask bias
        #pragma unroll
        for (int hh = 0; hh < 4; hh++) {
            int h = h0 + hh;
            #pragma unroll
            for (int q2 = 0; q2 < 2; q2++) {
                int row = jb + qr + (q2 << 3);
                float s = 0.f;
                #pragma unroll
                for (int np = 0; np < 2; np++) {
                    int nt = hh * 2 + np;
                    #pragma unroll
                    for (int c0 = 0; c0 < 2; c0++) {
                        int m = mb + nt * 8 + qc + c0;
                        float p = acc[nt][q2 * 2 + c0] + sPre[m]
                                + __bfloat162float(sP[row * 136 + m]);
                        p = (p > 0.f) ? p : 0.01f * p;
                        s = fmaf(p, sAw[m], s);
                    }
                }
                s += __shfl_xor_sync(0xffffffffu, s, 1);
                s += __shfl_xor_sync(0xffffffffu, s, 2);
                if ((lane & 3) == 0) {
                    float bias = (sAdj[j0 + row] - 1.0f) * 1e9f;
                    g_logits[((size_t)((b * 8 + h) * 512 + i)) * 512 + j0 + row] =
                        s + sAb[h] + bias;
                }
            }
        }
    }
}

// ---------------- kernel 4: softmax over j (mask already folded) ----------------
__global__ void softmax_k() {
    int r = blockIdx.x;            // (b*8+h)*512 + i
    float* row = g_logits + (size_t)r * 512;
    int t = threadIdx.x;
    __shared__ float red[4];

    float x[4];
    #pragma unroll
    for (int ii = 0; ii < 4; ii++) x[ii] = row[t + ii * 128];
    float m = fmaxf(fmaxf(x[0], x[1]), fmaxf(x[2], x[3]));
    #pragma unroll
    for (int off = 16; off > 0; off >>= 1) m = fmaxf(m, __shfl_xor_sync(0xffffffffu, m, off));
    if ((t & 31) == 0) red[t >> 5] = m;
    __syncthreads();
    m = fmaxf(fmaxf(red[0], red[1]), fmaxf(red[2], red[3]));

    float e[4], s = 0.f;
    #pragma unroll
    for (int ii = 0; ii < 4; ii++) { e[ii] = __expf(x[ii] - m); s += e[ii]; }
    #pragma unroll
    for (int off = 16; off > 0; off >>= 1) s += __shfl_xor_sync(0xffffffffu, s, off);
    __syncthreads();
    if ((t & 31) == 0) red[t >> 5] = s;
    __syncthreads();
    s = red[0] + red[1] + red[2] + red[3];
    float inv = 1.0f / s;
    #pragma unroll
    for (int ii = 0; ii < 4; ii++) row[t + ii * 128] = e[ii] * inv;
}

// ---------------- kernel 5: coefs @ values + skip + relu + layernorm ----------------
// block = (b, 2 i's), 512 threads. thread = (j-quarter, o).
__global__ void __launch_bounds__(512) out_k(const float* __restrict__ ln_scale,
                                             const float* __restrict__ ln_offset,
                                             float* __restrict__ out) {
    __shared__ float sc[2][8][512];      // 32 KB
    __shared__ float sacc[4][2][128];    // 4 KB
    __shared__ float red[2][4][2];
    int blk = blockIdx.x;
    int b = blk >> 8;                    // 0..3
    int i0 = (blk & 255) * 2;            // 0..510
    int t = threadIdx.x;

    { // stage coefs for 2 i's x 8 heads x 512 j  (2048 float4)
        float4* scv = (float4*)sc;
        const float4* gl = (const float4*)g_logits;
        #pragma unroll
        for (int it = 0; it < 4; it++) {
            int q = t + it * 512;               // 0..2047
            int ii = q >> 10;
            int h = (q >> 7) & 7;
            int c = q & 127;
            scv[q] = gl[((size_t)((b * 8 + h) * 512) + i0 + ii) * 128 + c];
        }
    }
    __syncthreads();

    {
        int o = t & 127;
        int jq = t >> 7;                        // 0..3 j-quarter
        int h = o >> 4;
        const float* vb = g_val + (size_t)b * 65536 + (size_t)(jq * 128) * 128 + o;
        const float* cf0 = &sc[0][h][jq * 128];
        const float* cf1 = &sc[1][h][jq * 128];
        float a0 = 0.f, a1 = 0.f;
        #pragma unroll 8
        for (int j = 0; j < 128; j++) {
            float v = vb[(size_t)j * 128];
            a0 = fmaf(cf0[j], v, a0);
            a1 = fmaf(cf1[j], v, a1);
        }
        sacc[jq][0][o] = a0;
        sacc[jq][1][o] = a1;
    }
    __syncthreads();

    int lane = t & 31;
    int o2 = t & 127;
    int i2 = (t >> 7) & 1;
    bool active = t < 256;
    float r = 0.f;
    size_t base = ((size_t)(b * 512) + i0 + i2) * 128 + o2;
    if (active) {
        r = sacc[0][i2][o2] + sacc[1][i2][o2] + sacc[2][i2][o2] + sacc[3][i2][o2]
          + g_skip[base];
        r = fmaxf(r, 0.f);
        float s1 = r, s2 = r * r;
        #pragma unroll
        for (int off = 16; off > 0; off >>= 1) {
            s1 += __shfl_xor_sync(0xffffffffu, s1, off);
            s2 += __shfl_xor_sync(0xffffffffu, s2, off);
        }
        if (lane == 0) {
            int wq = (t >> 5) & 3;
            red[i2][wq][0] = s1;
            red[i2][wq][1] = s2;
        }
    }
    __syncthreads();
    if (active) {
        float s1 = red[i2][0][0] + red[i2][1][0] + red[i2][2][0] + red[i2][3][0];
        float s2 = red[i2][0][1] + red[i2][1][1] + red[i2][2][1] + red[i2][3][1];
        float mean = s1 * (1.0f / 128.0f);
        float var = s2 * (1.0f / 128.0f) - mean * mean;
        out[base] = (r - mean) * rsqrtf(var + 1e-5f) * ln_scale[o2] + ln_offset[o2];
    }
}

// ---------------- launch ----------------
extern "C" void kernel_launch(void* const* d_in, const int* in_sizes, int n_in,
                              void* d_out, int out_size) {
    const float* node   = (const float*)d_in[0];
    const float* edge   = (const float*)d_in[1];
    const float* graph  = (const float*)d_in[2];
    const float* adj    = (const float*)d_in[3];
    const float* m_w    = (const float*)d_in[5];
    const float* m_b    = (const float*)d_in[6];
    const float* skip_w = (const float*)d_in[7];
    const float* skip_b = (const float*)d_in[8];
    const float* w1_w   = (const float*)d_in[9];
    const float* w1_b   = (const float*)d_in[10];
    const float* w2_w   = (const float*)d_in[11];
    const float* w2_b   = (const float*)d_in[12];
    const float* we_w   = (const float*)d_in[13];
    const float* we_b   = (const float*)d_in[14];
    const float* wg_w   = (const float*)d_in[15];
    const float* wg_b   = (const float*)d_in[16];
    const float* a_w    = (const float*)d_in[17];
    const float* a_b    = (const float*)d_in[18];
    const float* ln_s   = (const float*)d_in[19];
    const float* ln_o   = (const float*)d_in[20];
    float* out = (float*)d_out;

    // sW 34816 + sE 17408 + sP 17408 + (128+128+8+512)*4 = 72736
    const int EDGE_SMEM = 72736;
    cudaFuncSetAttribute(edge_k, cudaFuncAttributeMaxDynamicSharedMemorySize, EDGE_SMEM);

    prep_k<<<8, 128>>>(graph, wg_w, wg_b, we_w);
    node_k<<<256, 128>>>(node, m_w, m_b, skip_w, skip_b, w1_w, w1_b, w2_w, w2_b, we_b);
    edge_k<<<2048, 256, EDGE_SMEM>>>(edge, adj, a_w, a_b);
    softmax_k<<<16384, 128>>>();
    out_k<<<1024, 512>>>(ln_s, ln_o, out);
}